// round 7
// baseline (speedup 1.0000x reference)
#include <cuda_runtime.h>

#define BB 64
#define TT 512
#define II 512
#define HH 1024

// h double buffer (fp32), barrier state — static device globals (no allocs).
__device__ float g_h[2][BB * HH];
__device__ unsigned g_count;
__device__ unsigned g_gen;

// ---------------------------------------------------------------------------
// Init: reset barrier generation each launch (graph-replay determinism) and
// load h_prev into buffer 0.
// ---------------------------------------------------------------------------
__global__ void rnn_init(const float* __restrict__ h_prev) {
    int i = blockIdx.x * blockDim.x + threadIdx.x;
    if (i == 0) { g_count = 0; g_gen = 0; }
    if (i < BB * HH) g_h[0][i] = h_prev[i];
}

// ---------------------------------------------------------------------------
// Phase 1: x_proj = inputs(32768x512) @ W_xh(512x1024) + b  -> written to out.
// Classic 128x128 SGEMM tile, 8x8 per-thread microtile, BK=16.
// ---------------------------------------------------------------------------
__global__ __launch_bounds__(256, 2) void xproj_gemm(
    const float* __restrict__ A, const float* __restrict__ W,
    const float* __restrict__ bias, float* __restrict__ C) {
    __shared__ float As[16][128];   // transposed A tile: As[k][m]
    __shared__ float Bs[16][128];   // Bs[k][n]

    const int tid = threadIdx.x;
    const int m0 = blockIdx.y * 128;
    const int n0 = blockIdx.x * 128;
    const int tx = tid & 15;        // n microtile
    const int ty = tid >> 4;        // m microtile

    const int aRow = tid >> 2;          // 0..63 (two passes of 64 rows)
    const int aK   = (tid & 3) * 4;     // k offset within 16
    const int bRow = tid >> 5;          // 0..7 (two passes of 8 k-rows)
    const int bC   = (tid & 31) * 4;    // col offset

    float acc[8][8];
#pragma unroll
    for (int i = 0; i < 8; i++)
#pragma unroll
        for (int j = 0; j < 8; j++) acc[i][j] = 0.f;

    for (int k0 = 0; k0 < II; k0 += 16) {
#pragma unroll
        for (int it = 0; it < 2; it++) {
            int row = aRow + it * 64;
            float4 v = *(const float4*)&A[(size_t)(m0 + row) * II + k0 + aK];
            As[aK + 0][row] = v.x;
            As[aK + 1][row] = v.y;
            As[aK + 2][row] = v.z;
            As[aK + 3][row] = v.w;
        }
#pragma unroll
        for (int it = 0; it < 2; it++) {
            int rr = bRow + it * 8;
            *(float4*)&Bs[rr][bC] =
                *(const float4*)&W[(size_t)(k0 + rr) * HH + n0 + bC];
        }
        __syncthreads();
#pragma unroll
        for (int kk = 0; kk < 16; kk++) {
            float a[8], b[8];
            *(float4*)&a[0] = *(const float4*)&As[kk][ty * 8];
            *(float4*)&a[4] = *(const float4*)&As[kk][ty * 8 + 4];
            *(float4*)&b[0] = *(const float4*)&Bs[kk][tx * 8];
            *(float4*)&b[4] = *(const float4*)&Bs[kk][tx * 8 + 4];
#pragma unroll
            for (int i = 0; i < 8; i++)
#pragma unroll
                for (int j = 0; j < 8; j++)
                    acc[i][j] += a[i] * b[j];
        }
        __syncthreads();
    }

#pragma unroll
    for (int i = 0; i < 8; i++) {
        int row = m0 + ty * 8 + i;
#pragma unroll
        for (int j = 0; j < 8; j++)
            acc[i][j] += bias[n0 + tx * 8 + j];
        *(float4*)&C[(size_t)row * HH + n0 + tx * 8]     = *(float4*)&acc[i][0];
        *(float4*)&C[(size_t)row * HH + n0 + tx * 8 + 4] = *(float4*)&acc[i][4];
    }
}

// ---------------------------------------------------------------------------
// Grid barrier: all 128 CTAs resident (128 <= 148 SMs, 1 CTA/SM).
// Producer: __syncthreads + gpu fence + atomic arrive.
// Consumer: volatile spin + gpu fence (CCTL.IVALL -> fresh L1 afterwards).
// Generation counter reset by rnn_init each launch.
// ---------------------------------------------------------------------------
__device__ __forceinline__ void grid_sync(unsigned target) {
    __syncthreads();
    if (threadIdx.x == 0) {
        __threadfence();  // publish this CTA's h stores
        unsigned prev = atomicAdd(&g_count, 1);
        if (prev == gridDim.x - 1) {
            atomicExch(&g_count, 0);
            __threadfence();
            atomicExch(&g_gen, target);  // release
        } else {
            while (*(volatile unsigned*)&g_gen < target) { }
        }
        __threadfence();  // gpu-scope fence -> L1D invalidate (CCTL.IVALL)
    }
    __syncthreads();
}

// FMA helper as a function, not a macro: avoids the parameter-name capture
// bug (a macro param named `w` clobbered `acc.w`), and lets ptxas schedule.
__device__ __forceinline__ void fma4(float4& acc, float s, const float4& wv) {
    acc.x += s * wv.x;
    acc.y += s * wv.y;
    acc.z += s * wv.z;
    acc.w += s * wv.w;
}

// ---------------------------------------------------------------------------
// Phase 2: persistent recurrence. 128 CTAs: blockIdx >> 4 -> 8-row batch tile,
// blockIdx & 15 -> 64-col hidden tile. 256 threads: tx (16) -> 4 cols each,
// ty (16): r = ty&7 (row), kh = ty>>3 (k split half). Per-thread: 4 partial
// dots over 512 k, then smem pairwise reduction, tanh, write h + out.
// x_proj lives in `out` and is overwritten in place by h.
// ---------------------------------------------------------------------------
__global__ __launch_bounds__(256, 1) void rnn_recur(
    const float* __restrict__ Whh, float* __restrict__ out) {
    __shared__ float Hs[8][HH];       // 32 KB: 8 batch rows of h
    __shared__ float4 Red[128];       // split-k reduction buffer

    const int tid = threadIdx.x;
    const int tx = tid & 15;
    const int ty = tid >> 4;
    const int r  = ty & 7;
    const int kh = ty >> 3;
    const int rowbase = (blockIdx.x >> 4) * 8;
    const int c = (blockIdx.x & 15) * 64 + tx * 4;
    const float* wbase = Whh + (size_t)(kh * 512) * HH + c;

    int cur = 0;
    for (int t = 0; t < TT; t++) {
        // Stage h tile (8 rows x 1024) into smem. Fresh from L2 (L1 was
        // invalidated by the barrier fence / per-launch flush).
        {
            const float4* src = (const float4*)(&g_h[cur][rowbase * HH]);
            float4* dst = (float4*)&Hs[0][0];
#pragma unroll
            for (int i = 0; i < 8; i++)
                dst[tid + i * 256] = src[tid + i * 256];
        }
        __syncthreads();

        float4 acc = make_float4(0.f, 0.f, 0.f, 0.f);
        const float* hk = &Hs[r][kh * 512];
#pragma unroll 2
        for (int k = 0; k < 512; k += 8) {
            float4 a0 = *(const float4*)(hk + k);
            float4 a1 = *(const float4*)(hk + k + 4);
            const float* wp = wbase + (size_t)k * HH;
            float4 w0 = *(const float4*)(wp + 0 * HH);
            float4 w1 = *(const float4*)(wp + 1 * HH);
            float4 w2 = *(const float4*)(wp + 2 * HH);
            float4 w3 = *(const float4*)(wp + 3 * HH);
            float4 w4 = *(const float4*)(wp + 4 * HH);
            float4 w5 = *(const float4*)(wp + 5 * HH);
            float4 w6 = *(const float4*)(wp + 6 * HH);
            float4 w7 = *(const float4*)(wp + 7 * HH);
            fma4(acc, a0.x, w0);
            fma4(acc, a0.y, w1);
            fma4(acc, a0.z, w2);
            fma4(acc, a0.w, w3);
            fma4(acc, a1.x, w4);
            fma4(acc, a1.y, w5);
            fma4(acc, a1.z, w6);
            fma4(acc, a1.w, w7);
        }

        // Reduce the two k-halves. Previous step's Red consumers finished
        // before the last grid_sync, so writing now is safe.
        if (kh) Red[tid - 128] = acc;
        __syncthreads();
        if (!kh) {
            float4 p = Red[tid];
            size_t oidx = ((size_t)(rowbase + r) * TT + t) * HH + c;
            float4 xp = *(const float4*)&out[oidx];
            float4 hv;
            hv.x = tanhf(acc.x + p.x + xp.x);
            hv.y = tanhf(acc.y + p.y + xp.y);
            hv.z = tanhf(acc.z + p.z + xp.z);
            hv.w = tanhf(acc.w + p.w + xp.w);
            *(float4*)&out[oidx] = hv;
            *(float4*)&g_h[cur ^ 1][(size_t)(rowbase + r) * HH + c] = hv;
        }

        grid_sync((unsigned)(t + 1));
        cur ^= 1;
    }
}

// ---------------------------------------------------------------------------
// inputs: d_in[0]=inputs (B,T,I) f32, d_in[1]=h_prev (B,H) f32,
//         d_in[2]=W_xh (I,H) f32, d_in[3]=W_hh (H,H) f32, d_in[4]=b_h (H) f32
// out: (B,T,H) f32
// ---------------------------------------------------------------------------
extern "C" void kernel_launch(void* const* d_in, const int* in_sizes, int n_in,
                              void* d_out, int out_size) {
    const float* x      = (const float*)d_in[0];
    const float* h_prev = (const float*)d_in[1];
    const float* W_xh   = (const float*)d_in[2];
    const float* W_hh   = (const float*)d_in[3];
    const float* b_h    = (const float*)d_in[4];
    float* out = (float*)d_out;

    (void)in_sizes; (void)n_in; (void)out_size;

    rnn_init<<<256, 256>>>(h_prev);
    xproj_gemm<<<dim3(HH / 128, (BB * TT) / 128), 256>>>(x, W_xh, b_h, out);
    rnn_recur<<<128, 256>>>(W_hh, out);
}

// round 10
// speedup vs baseline: 1.4100x; 1.4100x over previous
#include <cuda_runtime.h>

#define BB 64
#define TT 512
#define II 512
#define HH 1024

// Recurrence tiling: 128 CTAs = 4 row-groups (16 rows) x 32 col-groups (32 cols).
#define RG_ROWS 16
#define CG_COLS 32
#define HS_STRIDE 1032   // padded h row stride (floats): bank shift 8/row

// h double buffer (fp32), barrier state — static device globals (no allocs).
__device__ float g_h[2][BB * HH];
__device__ unsigned g_count;
__device__ unsigned g_gen;

// ---------------------------------------------------------------------------
// Packed f32x2 helpers (Blackwell FFMA2 — ptxas never auto-fuses; PTX only).
// ---------------------------------------------------------------------------
__device__ __forceinline__ unsigned long long pack2(float v) {
    unsigned long long r;
    asm("mov.b64 %0, {%1, %1};" : "=l"(r) : "f"(v));
    return r;
}
__device__ __forceinline__ void fma2(unsigned long long& d,
                                     unsigned long long a,
                                     unsigned long long b) {
    asm("fma.rn.f32x2 %0, %1, %2, %0;" : "+l"(d) : "l"(a), "l"(b));
}
__device__ __forceinline__ void add2(unsigned long long& d,
                                     unsigned long long a) {
    asm("add.rn.f32x2 %0, %0, %1;" : "+l"(d) : "l"(a));
}
__device__ __forceinline__ void unpack2(unsigned long long v, float& lo, float& hi) {
    asm("mov.b64 {%0, %1}, %2;" : "=f"(lo), "=f"(hi) : "l"(v));
}
__device__ __forceinline__ unsigned long long dl(double d) {
    return __double_as_longlong(d);
}

// ---------------------------------------------------------------------------
// Init: reset barrier generation each launch (graph-replay determinism) and
// load h_prev into buffer 0.
// ---------------------------------------------------------------------------
__global__ void rnn_init(const float* __restrict__ h_prev) {
    int i = blockIdx.x * blockDim.x + threadIdx.x;
    if (i == 0) { g_count = 0; g_gen = 0; }
    if (i < BB * HH) g_h[0][i] = h_prev[i];
}

// ---------------------------------------------------------------------------
// Phase 1: x_proj = inputs(32768x512) @ W_xh(512x1024) + b  -> written to out.
// 128x128 tile, 8x8 microtile, BK=16, inner product via packed FFMA2.
// ---------------------------------------------------------------------------
__global__ __launch_bounds__(256, 2) void xproj_gemm(
    const float* __restrict__ A, const float* __restrict__ W,
    const float* __restrict__ bias, float* __restrict__ C) {
    __shared__ __align__(16) float As[16][128];   // As[k][m]
    __shared__ __align__(16) float Bs[16][128];   // Bs[k][n]

    const int tid = threadIdx.x;
    const int m0 = blockIdx.y * 128;
    const int n0 = blockIdx.x * 128;
    const int tx = tid & 15;        // n microtile
    const int ty = tid >> 4;        // m microtile

    const int aRow = tid >> 2;
    const int aK   = (tid & 3) * 4;
    const int bRow = tid >> 5;
    const int bC   = (tid & 31) * 4;

    // acc2[i][j2] holds (col 2*j2, col 2*j2+1) packed f32x2 for row i.
    unsigned long long acc2[8][4];
#pragma unroll
    for (int i = 0; i < 8; i++)
#pragma unroll
        for (int j = 0; j < 4; j++) acc2[i][j] = 0ull;

    for (int k0 = 0; k0 < II; k0 += 16) {
#pragma unroll
        for (int it = 0; it < 2; it++) {
            int row = aRow + it * 64;
            float4 v = *(const float4*)&A[(size_t)(m0 + row) * II + k0 + aK];
            As[aK + 0][row] = v.x;
            As[aK + 1][row] = v.y;
            As[aK + 2][row] = v.z;
            As[aK + 3][row] = v.w;
        }
#pragma unroll
        for (int it = 0; it < 2; it++) {
            int rr = bRow + it * 8;
            *(float4*)&Bs[rr][bC] =
                *(const float4*)&W[(size_t)(k0 + rr) * HH + n0 + bC];
        }
        __syncthreads();
#pragma unroll
        for (int kk = 0; kk < 16; kk++) {
            float a[8];
            *(float4*)&a[0] = *(const float4*)&As[kk][ty * 8];
            *(float4*)&a[4] = *(const float4*)&As[kk][ty * 8 + 4];
            double2 bx = *(const double2*)&Bs[kk][tx * 8];
            double2 by = *(const double2*)&Bs[kk][tx * 8 + 4];
            unsigned long long b01 = dl(bx.x), b23 = dl(bx.y);
            unsigned long long b45 = dl(by.x), b67 = dl(by.y);
#pragma unroll
            for (int i = 0; i < 8; i++) {
                unsigned long long ap = pack2(a[i]);
                fma2(acc2[i][0], ap, b01);
                fma2(acc2[i][1], ap, b23);
                fma2(acc2[i][2], ap, b45);
                fma2(acc2[i][3], ap, b67);
            }
        }
        __syncthreads();
    }

#pragma unroll
    for (int i = 0; i < 8; i++) {
        int row = m0 + ty * 8 + i;
        float c[8];
#pragma unroll
        for (int j = 0; j < 4; j++) unpack2(acc2[i][j], c[2 * j], c[2 * j + 1]);
#pragma unroll
        for (int j = 0; j < 8; j++) c[j] += bias[n0 + tx * 8 + j];
        *(float4*)&C[(size_t)row * HH + n0 + tx * 8]     = *(float4*)&c[0];
        *(float4*)&C[(size_t)row * HH + n0 + tx * 8 + 4] = *(float4*)&c[4];
    }
}

// ---------------------------------------------------------------------------
// Grid barrier: all 128 CTAs resident (1 CTA/SM). Release fence before the
// arrive publishes h stores; consumers read the fresh h via __ldcg (L1 bypass)
// so NO trailing acquire fence (no CCTL.IVALL) is needed — L1 stays warm for
// the CTA-private out tile. g_gen is reset by rnn_init every launch.
// ---------------------------------------------------------------------------
__device__ __forceinline__ void grid_sync(unsigned target) {
    __syncthreads();
    if (threadIdx.x == 0) {
        __threadfence();  // release: publish this CTA's g_h stores to L2
        unsigned prev = atomicAdd(&g_count, 1);
        if (prev == gridDim.x - 1) {
            atomicExch(&g_count, 0);
            __threadfence();
            atomicExch(&g_gen, target);  // release the pack
        } else {
            while (*(volatile unsigned*)&g_gen < target) { }
        }
    }
    __syncthreads();
}

// ---------------------------------------------------------------------------
// Phase 2: persistent recurrence, W_hh SMEM-RESIDENT across all 512 steps.
//
// CTA: 16 batch rows x 32 hidden cols. SMEM: W tile 1024x32 f32 (128 KB,
// loaded once), h tile 16x1032 f32 (64.5 KB, staged per step via __ldcg),
// 2 KB reduction buffer. ~199 KB dynamic smem, occupancy 1 (by design).
//
// Threads (256): tid = rhi*64 + kh*32 + cg*4 + rlo
//   r = rhi*4+rlo (16 rows), cg (8 groups of 4 cols), kh (split-k half).
// Warp = fixed (rhi,kh), lanes = 8 cg x 4 rlo:
//   W LDS.128: 8 distinct addrs, banks cg*4.. -> all 32 banks, 1 phase.
//   h LDS.128: 4 distinct addrs, row stride 1032 -> banks +8/row, 1 phase.
// Inner product uses packed FFMA2 (2 cols per instruction).
// ---------------------------------------------------------------------------
__global__ __launch_bounds__(256, 1) void rnn_recur(
    const float* __restrict__ Whh, float* __restrict__ out) {
    extern __shared__ __align__(16) float smem_dyn[];
    float* ws = smem_dyn;                         // [1024][32]
    float* hs = ws + 1024 * CG_COLS;              // [16][1032]
    ulonglong2* red = (ulonglong2*)(hs + RG_ROWS * HS_STRIDE);  // [128]

    const int tid = threadIdx.x;
    const int rlo = tid & 3;
    const int cg  = (tid >> 2) & 7;
    const int kh  = (tid >> 5) & 1;
    const int rhi = tid >> 6;
    const int r   = rhi * 4 + rlo;

    const int rowbase = (blockIdx.x >> 5) * RG_ROWS;   // 4 row groups
    const int colbase = (blockIdx.x & 31) * CG_COLS;   // 32 col groups
    const int c = colbase + cg * 4;

    // --- Prologue: load W tile (1024 x 32) into smem, once. ---
    {
        const float4* wsrc0 = (const float4*)(Whh + colbase);
        float4* wdst = (float4*)ws;
#pragma unroll
        for (int i = 0; i < 32; i++) {
            int idx4 = tid + i * 256;           // 8192 float4 total
            int k  = idx4 >> 3;                 // 8 float4 per W row
            int c4 = idx4 & 7;
            wdst[idx4] = wsrc0[(size_t)k * (HH / 4) + c4];
        }
    }
    __syncthreads();

    const float4* hp4 = (const float4*)(hs + (size_t)r * HS_STRIDE + kh * 512);
    const float*  wpf = ws + kh * 512 * CG_COLS + cg * 4;

    int cur = 0;
    for (int t = 0; t < TT; t++) {
        // --- Stage h tile (16 rows x 1024) into padded smem; L1-bypass. ---
        {
            const float4* src = (const float4*)(&g_h[cur][rowbase * HH]);
#pragma unroll
            for (int i = 0; i < 16; i++) {
                int idx4 = tid + i * 256;       // 4096 float4 total
                int row  = idx4 >> 8;           // 256 float4 per h row
                int k4   = idx4 & 255;
                float4 v = __ldcg(&src[idx4]);
                ((float4*)hs)[row * (HS_STRIDE / 4) + k4] = v;
            }
        }

        // Prefetch x_proj for the epilogue (independent of h).
        float4 xp;
        size_t oidx = 0;
        if (!kh) {
            oidx = ((size_t)(rowbase + r) * TT + t) * HH + c;
            xp = *(const float4*)&out[oidx];
        }
        __syncthreads();

        // --- GEMM inner: 4 cols (2 packed pairs) x 512 k, all from smem. ---
        unsigned long long a01 = 0ull, a23 = 0ull;
#pragma unroll 2
        for (int k8 = 0; k8 < 64; k8++) {
            float4 h0 = hp4[k8 * 2];
            float4 h1 = hp4[k8 * 2 + 1];
            const float* wk = wpf + k8 * 8 * CG_COLS;
            double2 w0 = *(const double2*)(wk + 0 * CG_COLS);
            double2 w1 = *(const double2*)(wk + 1 * CG_COLS);
            double2 w2 = *(const double2*)(wk + 2 * CG_COLS);
            double2 w3 = *(const double2*)(wk + 3 * CG_COLS);
            double2 w4 = *(const double2*)(wk + 4 * CG_COLS);
            double2 w5 = *(const double2*)(wk + 5 * CG_COLS);
            double2 w6 = *(const double2*)(wk + 6 * CG_COLS);
            double2 w7 = *(const double2*)(wk + 7 * CG_COLS);
            unsigned long long hp;
            hp = pack2(h0.x); fma2(a01, hp, dl(w0.x)); fma2(a23, hp, dl(w0.y));
            hp = pack2(h0.y); fma2(a01, hp, dl(w1.x)); fma2(a23, hp, dl(w1.y));
            hp = pack2(h0.z); fma2(a01, hp, dl(w2.x)); fma2(a23, hp, dl(w2.y));
            hp = pack2(h0.w); fma2(a01, hp, dl(w3.x)); fma2(a23, hp, dl(w3.y));
            hp = pack2(h1.x); fma2(a01, hp, dl(w4.x)); fma2(a23, hp, dl(w4.y));
            hp = pack2(h1.y); fma2(a01, hp, dl(w5.x)); fma2(a23, hp, dl(w5.y));
            hp = pack2(h1.z); fma2(a01, hp, dl(w6.x)); fma2(a23, hp, dl(w6.y));
            hp = pack2(h1.w); fma2(a01, hp, dl(w7.x)); fma2(a23, hp, dl(w7.y));
        }

        // --- Split-k reduce (2 halves) via smem. ---
        if (kh) red[r * 8 + cg] = make_ulonglong2(a01, a23);
        __syncthreads();

        if (!kh) {
            ulonglong2 p = red[r * 8 + cg];
            add2(a01, p.x);
            add2(a23, p.y);
            float s0, s1, s2, s3;
            unpack2(a01, s0, s1);
            unpack2(a23, s2, s3);
            float4 hv;
            hv.x = tanhf(s0 + xp.x);
            hv.y = tanhf(s1 + xp.y);
            hv.z = tanhf(s2 + xp.z);
            hv.w = tanhf(s3 + xp.w);
            *(float4*)&out[oidx] = hv;
            *(float4*)&g_h[cur ^ 1][(size_t)(rowbase + r) * HH + c] = hv;
        }

        grid_sync((unsigned)(t + 1));
        cur ^= 1;
    }
}

// ---------------------------------------------------------------------------
// inputs: d_in[0]=inputs (B,T,I) f32, d_in[1]=h_prev (B,H) f32,
//         d_in[2]=W_xh (I,H) f32, d_in[3]=W_hh (H,H) f32, d_in[4]=b_h (H) f32
// out: (B,T,H) f32
// ---------------------------------------------------------------------------
extern "C" void kernel_launch(void* const* d_in, const int* in_sizes, int n_in,
                              void* d_out, int out_size) {
    const float* x      = (const float*)d_in[0];
    const float* h_prev = (const float*)d_in[1];
    const float* W_xh   = (const float*)d_in[2];
    const float* W_hh   = (const float*)d_in[3];
    const float* b_h    = (const float*)d_in[4];
    float* out = (float*)d_out;

    (void)in_sizes; (void)n_in; (void)out_size;

    // 128 KB (W) + 64.5 KB (h padded) + 2 KB (red) = 199168 B dynamic smem.
    const int smem_bytes = (1024 * CG_COLS + RG_ROWS * HS_STRIDE) * 4 + 2048;
    cudaFuncSetAttribute(rnn_recur, cudaFuncAttributeMaxDynamicSharedMemorySize,
                         smem_bytes);

    rnn_init<<<256, 256>>>(h_prev);
    xproj_gemm<<<dim3(HH / 128, (BB * TT) / 128), 256>>>(x, W_xh, b_h, out);
    rnn_recur<<<128, 256, smem_bytes>>>(W_hh, out);
}